// round 1
// baseline (speedup 1.0000x reference)
#include <cuda_runtime.h>
#include <math.h>

// Problem constants
#define B_  2
#define S_  2048
#define HID_ 2048
#define NH_ 16
#define HD_ 128
#define M_  (B_ * S_)     // 4096 rows for projection GEMMs
#define K_  HID_          // 2048

// Scratch (allocation-free rule: __device__ globals)
__device__ float g_q[B_ * NH_ * S_ * HD_];   // [b,h,s,d]
__device__ float g_k[B_ * NH_ * S_ * HD_];
__device__ float g_v[B_ * NH_ * S_ * HD_];
__device__ float g_ctx[B_ * S_ * HID_];      // [b,s,h*HD+d]

// ---------------------------------------------------------------------------
// SGEMM  C = A * W^T
// A: [M,K] row-major, W: [N,K] row-major.
// layout 0: C[m*N + n]        (plain)
// layout 1: C[((b*NH+h)*S+s)*HD + d]   with m=b*S+s, n=h*HD+d
// Tiles: 128x128x8, 256 threads, 8x8 per thread.
// ---------------------------------------------------------------------------
#define BM 128
#define BN 128
#define BK 8

__global__ __launch_bounds__(256, 2)
void sgemm_nt(const float* __restrict__ A, const float* __restrict__ W,
              float* __restrict__ C, int M, int N, int K, int layout)
{
    __shared__ float As[BK][BM];
    __shared__ float Bs[BK][BN];

    const int tid = threadIdx.x;
    const int tx = tid & 15;        // 0..15 -> N direction
    const int ty = tid >> 4;        // 0..15 -> M direction
    const int m0 = blockIdx.y * BM;
    const int n0 = blockIdx.x * BN;

    float acc[8][8];
#pragma unroll
    for (int i = 0; i < 8; i++)
#pragma unroll
        for (int j = 0; j < 8; j++) acc[i][j] = 0.0f;

    const int lr = tid >> 1;         // 0..127 (tile row)
    const int lc = (tid & 1) * 4;    // 0 or 4 (k offset)
    const float* Aptr = A + (size_t)(m0 + lr) * K + lc;
    const float* Wptr = W + (size_t)(n0 + lr) * K + lc;

    for (int k0 = 0; k0 < K; k0 += BK) {
        float4 av = *(const float4*)(Aptr + k0);
        float4 bv = *(const float4*)(Wptr + k0);
        __syncthreads();
        As[lc + 0][lr] = av.x; As[lc + 1][lr] = av.y;
        As[lc + 2][lr] = av.z; As[lc + 3][lr] = av.w;
        Bs[lc + 0][lr] = bv.x; Bs[lc + 1][lr] = bv.y;
        Bs[lc + 2][lr] = bv.z; Bs[lc + 3][lr] = bv.w;
        __syncthreads();
#pragma unroll
        for (int kk = 0; kk < BK; kk++) {
            float a[8], b[8];
            *(float4*)&a[0] = *(const float4*)&As[kk][ty * 8];
            *(float4*)&a[4] = *(const float4*)&As[kk][ty * 8 + 4];
            *(float4*)&b[0] = *(const float4*)&Bs[kk][tx * 8];
            *(float4*)&b[4] = *(const float4*)&Bs[kk][tx * 8 + 4];
#pragma unroll
            for (int i = 0; i < 8; i++)
#pragma unroll
                for (int j = 0; j < 8; j++)
                    acc[i][j] = fmaf(a[i], b[j], acc[i][j]);
        }
    }

#pragma unroll
    for (int i = 0; i < 8; i++) {
        const int m = m0 + ty * 8 + i;
#pragma unroll
        for (int j = 0; j < 8; j++) {
            const int n = n0 + tx * 8 + j;
            if (layout == 0) {
                C[(size_t)m * N + n] = acc[i][j];
            } else {
                const int b = m >> 11;          // /S_
                const int s = m & (S_ - 1);
                const int h = n >> 7;           // /HD_
                const int d = n & (HD_ - 1);
                C[(((size_t)(b * NH_ + h)) * S_ + s) * HD_ + d] = acc[i][j];
            }
        }
    }
}

// ---------------------------------------------------------------------------
// RoPE in place on g_q / g_k ([b,h,s,d] layout). One thread per (b,h,s,d<64).
// ---------------------------------------------------------------------------
__global__ void rope_kernel(float* __restrict__ q, float* __restrict__ k,
                            const int* __restrict__ pos_ids)
{
    const int idx = blockIdx.x * blockDim.x + threadIdx.x;
    const int total = B_ * NH_ * S_ * (HD_ / 2);
    if (idx >= total) return;
    const int d = idx & 63;
    int t = idx >> 6;
    const int s = t & (S_ - 1);
    t >>= 11;
    const int h = t & (NH_ - 1);
    const int b = t >> 4;

    const int p = pos_ids[b * S_ + s];
    // inv_freq = 10000^(-2d/HD), computed in double for a tight fp32 round
    const float inv_f = (float)pow(10000.0, -(double)(2 * d) / (double)HD_);
    const float ang = (float)p * inv_f;
    float sn, cs;
    sincosf(ang, &sn, &cs);

    const size_t base = (((size_t)(b * NH_ + h)) * S_ + s) * HD_ + d;
    const float q1 = q[base], q2 = q[base + 64];
    q[base]      = q1 * cs - q2 * sn;
    q[base + 64] = q2 * cs + q1 * sn;
    const float k1 = k[base], k2 = k[base + 64];
    k[base]      = k1 * cs - k2 * sn;
    k[base + 64] = k2 * cs + k1 * sn;
}

// ---------------------------------------------------------------------------
// Flash attention (fp32, causal). 64 q-rows per block, 64-key tiles, HD=128.
// 256 threads as (ty 0..15) x (tx 0..15). Thread owns q-rows ty*4..+3;
// scores cols tx*4..+3; output cols tx*8..+7.
// K stored transposed in smem (Kts[kk][row], stride 68) for conflict-free
// per-thread float4 column loads.
// Output written to g_ctx in [b,s,h,d] layout for the final projection.
// ---------------------------------------------------------------------------
#define FTILE 64
#define KTS_STRIDE 68

__global__ __launch_bounds__(256, 1)
void flash_attn(const float* __restrict__ Qg, const float* __restrict__ Kg,
                const float* __restrict__ Vg, float* __restrict__ ctx)
{
    extern __shared__ float sm[];
    float* Qs  = sm;                         // 64*128
    float* Kts = Qs + 64 * 128;              // 128*68
    float* Vs  = Kts + 128 * KTS_STRIDE;     // 64*128
    float* Ps  = Vs + 64 * 128;              // 64*64

    const int tid = threadIdx.x;
    const int tx = tid & 15;
    const int ty = tid >> 4;
    const int qt = blockIdx.x;              // q tile index, 0..31
    const int bh = blockIdx.y;              // b*NH + h
    const size_t base = (size_t)bh * S_ * HD_;
    const float* Qp = Qg + base + (size_t)qt * FTILE * HD_;

    // Load Q tile
    for (int i = tid; i < FTILE * 32; i += 256) {
        const int r = i >> 5, c4 = (i & 31) << 2;
        *(float4*)&Qs[r * 128 + c4] = *(const float4*)&Qp[(size_t)r * HD_ + c4];
    }

    float m_i[4], l_i[4], acc[4][8];
#pragma unroll
    for (int r = 0; r < 4; r++) {
        m_i[r] = -3.0e30f;
        l_i[r] = 0.0f;
#pragma unroll
        for (int c = 0; c < 8; c++) acc[r][c] = 0.0f;
    }

    const float SCALE = 0.08838834764831845f;   // 1/sqrt(128)

    for (int j = 0; j <= qt; j++) {
        __syncthreads();   // protect Kts/Vs/Ps reuse
        const float* Kp = Kg + base + (size_t)j * FTILE * HD_;
        const float* Vp = Vg + base + (size_t)j * FTILE * HD_;
        for (int i = tid; i < FTILE * 32; i += 256) {
            const int r = i >> 5, c4 = (i & 31) << 2;
            const float4 kv = *(const float4*)&Kp[(size_t)r * HD_ + c4];
            Kts[(c4 + 0) * KTS_STRIDE + r] = kv.x;
            Kts[(c4 + 1) * KTS_STRIDE + r] = kv.y;
            Kts[(c4 + 2) * KTS_STRIDE + r] = kv.z;
            Kts[(c4 + 3) * KTS_STRIDE + r] = kv.w;
            *(float4*)&Vs[r * 128 + c4] = *(const float4*)&Vp[(size_t)r * HD_ + c4];
        }
        __syncthreads();

        // scores: sreg[r][c] = Q[ty*4+r] . K[tx*4+c]
        float sreg[4][4];
#pragma unroll
        for (int r = 0; r < 4; r++)
#pragma unroll
            for (int c = 0; c < 4; c++) sreg[r][c] = 0.0f;

#pragma unroll 4
        for (int kk = 0; kk < HD_; kk++) {
            const float4 kv = *(const float4*)&Kts[kk * KTS_STRIDE + tx * 4];
            float qv[4];
#pragma unroll
            for (int r = 0; r < 4; r++) qv[r] = Qs[(ty * 4 + r) * 128 + kk];
#pragma unroll
            for (int r = 0; r < 4; r++) {
                sreg[r][0] = fmaf(qv[r], kv.x, sreg[r][0]);
                sreg[r][1] = fmaf(qv[r], kv.y, sreg[r][1]);
                sreg[r][2] = fmaf(qv[r], kv.z, sreg[r][2]);
                sreg[r][3] = fmaf(qv[r], kv.w, sreg[r][3]);
            }
        }

        // scale + causal mask (only the diagonal tile needs it)
        const bool diag = (j == qt);
#pragma unroll
        for (int r = 0; r < 4; r++) {
            const int qrow = qt * FTILE + ty * 4 + r;
#pragma unroll
            for (int c = 0; c < 4; c++) {
                sreg[r][c] *= SCALE;
                if (diag) {
                    const int kcol = j * FTILE + tx * 4 + c;
                    if (kcol > qrow) sreg[r][c] = -1.0e30f;
                }
            }
        }

        // online softmax per row (reduce over tx via width-16 shfl)
#pragma unroll
        for (int r = 0; r < 4; r++) {
            float mloc = fmaxf(fmaxf(sreg[r][0], sreg[r][1]),
                               fmaxf(sreg[r][2], sreg[r][3]));
#pragma unroll
            for (int off = 8; off > 0; off >>= 1)
                mloc = fmaxf(mloc, __shfl_xor_sync(0xffffffffu, mloc, off, 16));
            const float mnew = fmaxf(m_i[r], mloc);
            const float corr = __expf(m_i[r] - mnew);
            float p[4], lloc = 0.0f;
#pragma unroll
            for (int c = 0; c < 4; c++) {
                p[c] = __expf(sreg[r][c] - mnew);
                lloc += p[c];
            }
#pragma unroll
            for (int off = 8; off > 0; off >>= 1)
                lloc += __shfl_xor_sync(0xffffffffu, lloc, off, 16);
            l_i[r] = l_i[r] * corr + lloc;
            m_i[r] = mnew;
#pragma unroll
            for (int c = 0; c < 8; c++) acc[r][c] *= corr;
#pragma unroll
            for (int c = 0; c < 4; c++)
                Ps[(ty * 4 + r) * FTILE + tx * 4 + c] = p[c];
        }
        __syncthreads();

        // O += P @ V ; thread owns O[ty*4+r][tx*8..+7]
#pragma unroll 4
        for (int c = 0; c < FTILE; c++) {
            const float4 v0 = *(const float4*)&Vs[c * 128 + tx * 8];
            const float4 v1 = *(const float4*)&Vs[c * 128 + tx * 8 + 4];
#pragma unroll
            for (int r = 0; r < 4; r++) {
                const float pv = Ps[(ty * 4 + r) * FTILE + c];
                acc[r][0] = fmaf(pv, v0.x, acc[r][0]);
                acc[r][1] = fmaf(pv, v0.y, acc[r][1]);
                acc[r][2] = fmaf(pv, v0.z, acc[r][2]);
                acc[r][3] = fmaf(pv, v0.w, acc[r][3]);
                acc[r][4] = fmaf(pv, v1.x, acc[r][4]);
                acc[r][5] = fmaf(pv, v1.y, acc[r][5]);
                acc[r][6] = fmaf(pv, v1.z, acc[r][6]);
                acc[r][7] = fmaf(pv, v1.w, acc[r][7]);
            }
        }
    }

    // epilogue: normalize and write to ctx [b,s,h,d]
    const int b = bh >> 4;          // /NH_
    const int h = bh & (NH_ - 1);
#pragma unroll
    for (int r = 0; r < 4; r++) {
        const float inv = 1.0f / l_i[r];
        const int srow = qt * FTILE + ty * 4 + r;
        float* dst = ctx + (((size_t)(b * S_ + srow)) * NH_ + h) * HD_ + tx * 8;
#pragma unroll
        for (int c = 0; c < 8; c++) dst[c] = acc[r][c] * inv;
    }
}

// ---------------------------------------------------------------------------
extern "C" void kernel_launch(void* const* d_in, const int* in_sizes, int n_in,
                              void* d_out, int out_size)
{
    const float* hs  = (const float*)d_in[0];
    // d_in[1] = attention_mask: deterministically causal, applied analytically
    const int*   pos = (const int*)d_in[2];
    const float* Wq  = (const float*)d_in[3];
    const float* Wk  = (const float*)d_in[4];
    const float* Wv  = (const float*)d_in[5];
    const float* Wo  = (const float*)d_in[6];
    float* out = (float*)d_out;

    float *q, *k, *v, *ctx;
    cudaGetSymbolAddress((void**)&q,   g_q);
    cudaGetSymbolAddress((void**)&k,   g_k);
    cudaGetSymbolAddress((void**)&v,   g_v);
    cudaGetSymbolAddress((void**)&ctx, g_ctx);

    const dim3 ggrid(HID_ / BN, M_ / BM);   // (16, 32)
    sgemm_nt<<<ggrid, 256>>>(hs, Wq, q, M_, HID_, K_, 1);
    sgemm_nt<<<ggrid, 256>>>(hs, Wk, k, M_, HID_, K_, 1);
    sgemm_nt<<<ggrid, 256>>>(hs, Wv, v, M_, HID_, K_, 1);

    const int rope_total = B_ * NH_ * S_ * (HD_ / 2);
    rope_kernel<<<(rope_total + 255) / 256, 256>>>(q, k, pos);

    const int smem = (64 * 128 + 128 * KTS_STRIDE + 64 * 128 + 64 * 64) * sizeof(float);
    static bool attr_set = false;
    if (!attr_set) {
        cudaFuncSetAttribute(flash_attn, cudaFuncAttributeMaxDynamicSharedMemorySize, smem);
        attr_set = true;
    }
    flash_attn<<<dim3(S_ / FTILE, B_ * NH_), 256, smem>>>(q, k, v, ctx);

    sgemm_nt<<<ggrid, 256>>>(ctx, Wo, out, M_, HID_, K_, 0);
}

// round 3
// speedup vs baseline: 1.6068x; 1.6068x over previous
#include <cuda_runtime.h>
#include <cuda_bf16.h>
#include <cstdint>
#include <cstddef>
#include <math.h>

// Problem constants
#define B_   2
#define S_   2048
#define HID_ 2048
#define NH_  16
#define HD_  128
#define M_   (B_ * S_)     // 4096
#define K_   HID_          // 2048
#define KEX_ (3 * K_)      // 6144 expanded (hi|lo|hi split)

// ---------------------------------------------------------------------------
// Scratch (allocation-free rule: __device__ globals)
// ---------------------------------------------------------------------------
__device__ float g_q[B_ * NH_ * S_ * HD_];     // [b,h,s,d] fp32
__device__ float g_k[B_ * NH_ * S_ * HD_];
__device__ float g_v[B_ * NH_ * S_ * HD_];
__device__ float g_ctx[B_ * S_ * HID_];        // [b,s,h*HD+d] fp32

__device__ __nv_bfloat16 g_aex[(size_t)M_ * KEX_];     // hs  expanded
__device__ __nv_bfloat16 g_cex[(size_t)M_ * KEX_];     // ctx expanded
__device__ __nv_bfloat16 g_wqe[(size_t)HID_ * KEX_];   // weights expanded
__device__ __nv_bfloat16 g_wke[(size_t)HID_ * KEX_];
__device__ __nv_bfloat16 g_wve[(size_t)HID_ * KEX_];
__device__ __nv_bfloat16 g_woe[(size_t)HID_ * KEX_];

// ---------------------------------------------------------------------------
// fp32 -> bf16 hi/lo split, expanded-K layout.
// mode 0 ("A" side):  [hi | lo | hi]
// mode 1 ("W" side):  [hi | hi | lo]
// So  A'·W'^T over Kex = Ah·Wh + Al·Wh + Ah·Wl  (exact to ~2^-18).
// ---------------------------------------------------------------------------
__global__ void split_expand(const float* __restrict__ X,
                             __nv_bfloat16* __restrict__ Y,
                             int total, int mode)
{
    int idx = blockIdx.x * blockDim.x + threadIdx.x;
    if (idx >= total) return;
    const int r = idx >> 11;           // / 2048
    const int k = idx & (K_ - 1);
    const float x = X[idx];
    const __nv_bfloat16 hi = __float2bfloat16_rn(x);
    const __nv_bfloat16 lo = __float2bfloat16_rn(x - __bfloat162float(hi));
    __nv_bfloat16* dst = Y + (size_t)r * KEX_ + k;
    if (mode == 0) { dst[0] = hi; dst[K_] = lo; dst[2 * K_] = hi; }
    else           { dst[0] = hi; dst[K_] = hi; dst[2 * K_] = lo; }
}

// ---------------------------------------------------------------------------
// bf16 mma.sync GEMM:  C[M,N] = A'[M,Kex] · W'[N,Kex]^T   (fp32 accumulate)
// Tiles 128x128x32, 8 warps (4m x 2n), warp tile 32x64, m16n8k16 mma.
// cp.async double buffering; smem rows padded to 40 bf16 (80B) ->
// conflict-free ldmatrix (80B stride cycles all banks across 8 rows).
// layout 0: C[m*N+n]; layout 1: scatter to [b,h,s,d].
// ---------------------------------------------------------------------------
#define GBM 128
#define GBN 128
#define GBK 32
#define LDP 40      // padded smem row length (bf16 elements)

__device__ __forceinline__ void cpasync16(void* smem_dst, const void* gsrc) {
    unsigned int d = (unsigned int)__cvta_generic_to_shared(smem_dst);
    asm volatile("cp.async.cg.shared.global [%0], [%1], 16;\n" :: "r"(d), "l"(gsrc));
}
__device__ __forceinline__ void cp_commit() {
    asm volatile("cp.async.commit_group;\n");
}

__device__ __forceinline__ void ldm_x4(unsigned int& r0, unsigned int& r1,
                                       unsigned int& r2, unsigned int& r3,
                                       unsigned int addr) {
    asm volatile("ldmatrix.sync.aligned.m8n8.x4.shared.b16 {%0,%1,%2,%3}, [%4];\n"
                 : "=r"(r0), "=r"(r1), "=r"(r2), "=r"(r3) : "r"(addr));
}

__device__ __forceinline__ void mma_bf16(float* c, const unsigned int* a,
                                         const unsigned int* b) {
    asm volatile(
        "mma.sync.aligned.m16n8k16.row.col.f32.bf16.bf16.f32 "
        "{%0,%1,%2,%3}, {%4,%5,%6,%7}, {%8,%9}, {%0,%1,%2,%3};\n"
        : "+f"(c[0]), "+f"(c[1]), "+f"(c[2]), "+f"(c[3])
        : "r"(a[0]), "r"(a[1]), "r"(a[2]), "r"(a[3]), "r"(b[0]), "r"(b[1]));
}

__global__ __launch_bounds__(256, 1)
void gemm_bf16(const __nv_bfloat16* __restrict__ A,
               const __nv_bfloat16* __restrict__ W,
               float* __restrict__ C, int N, int Kex, int layout)
{
    __shared__ __nv_bfloat16 As[2][GBM * LDP];
    __shared__ __nv_bfloat16 Bs[2][GBN * LDP];

    const int tid  = threadIdx.x;
    const int lane = tid & 31;
    const int w    = tid >> 5;
    const int wm   = (w >> 1) << 5;   // 0,32,64,96
    const int wn   = (w & 1) << 6;    // 0,64
    const int m0   = blockIdx.y * GBM;
    const int n0   = blockIdx.x * GBN;

    float acc[2][8][4];
#pragma unroll
    for (int mi = 0; mi < 2; mi++)
#pragma unroll
        for (int ni = 0; ni < 8; ni++)
#pragma unroll
            for (int e = 0; e < 4; e++) acc[mi][ni][e] = 0.0f;

    // load mapping: 512 16B chunks per matrix (128 rows x 4 chunks), 2/thread
    const int r0 = tid >> 2, c0 = tid & 3;
    const int r1 = r0 + 64,  c1 = c0;

    const int NT = Kex / GBK;

    // stage-0 prefetch
    cpasync16(&As[0][r0 * LDP + c0 * 8], A + (size_t)(m0 + r0) * Kex + c0 * 8);
    cpasync16(&As[0][r1 * LDP + c1 * 8], A + (size_t)(m0 + r1) * Kex + c1 * 8);
    cpasync16(&Bs[0][r0 * LDP + c0 * 8], W + (size_t)(n0 + r0) * Kex + c0 * 8);
    cpasync16(&Bs[0][r1 * LDP + c1 * 8], W + (size_t)(n0 + r1) * Kex + c1 * 8);
    cp_commit();

    const unsigned int sA = (unsigned int)__cvta_generic_to_shared(&As[0][0]);
    const unsigned int sB = (unsigned int)__cvta_generic_to_shared(&Bs[0][0]);
    const unsigned int stA = GBM * LDP * 2;   // bytes per A stage
    const unsigned int stB = GBN * LDP * 2;

    for (int kt = 0; kt < NT; kt++) {
        if (kt + 1 < NT) {
            const int st = (kt + 1) & 1;
            const int k0 = (kt + 1) * GBK;
            cpasync16(&As[st][r0 * LDP + c0 * 8], A + (size_t)(m0 + r0) * Kex + k0 + c0 * 8);
            cpasync16(&As[st][r1 * LDP + c1 * 8], A + (size_t)(m0 + r1) * Kex + k0 + c1 * 8);
            cpasync16(&Bs[st][r0 * LDP + c0 * 8], W + (size_t)(n0 + r0) * Kex + k0 + c0 * 8);
            cpasync16(&Bs[st][r1 * LDP + c1 * 8], W + (size_t)(n0 + r1) * Kex + k0 + c1 * 8);
            cp_commit();
            asm volatile("cp.async.wait_group 1;\n");
        } else {
            asm volatile("cp.async.wait_group 0;\n");
        }
        __syncthreads();

        const int st = kt & 1;
        const unsigned int aBase = sA + st * stA;
        const unsigned int bBase = sB + st * stB;

#pragma unroll
        for (int ks = 0; ks < 2; ks++) {
            unsigned int afr[2][4], bfr[8][2];
#pragma unroll
            for (int mi = 0; mi < 2; mi++) {
                const int row = wm + mi * 16 + (lane & 15);
                const unsigned int addr =
                    aBase + (unsigned int)(row * LDP + ks * 16 + (lane >> 4) * 8) * 2;
                ldm_x4(afr[mi][0], afr[mi][1], afr[mi][2], afr[mi][3], addr);
            }
#pragma unroll
            for (int p = 0; p < 4; p++) {
                const int nrow = wn + p * 16 + (lane & 7) + ((lane >> 4) << 3);
                const int chunk = (lane >> 3) & 1;
                const unsigned int addr =
                    bBase + (unsigned int)(nrow * LDP + ks * 16 + chunk * 8) * 2;
                ldm_x4(bfr[2 * p][0], bfr[2 * p][1], bfr[2 * p + 1][0], bfr[2 * p + 1][1], addr);
            }
#pragma unroll
            for (int mi = 0; mi < 2; mi++)
#pragma unroll
                for (int ni = 0; ni < 8; ni++)
                    mma_bf16(acc[mi][ni], afr[mi], bfr[ni]);
        }
        __syncthreads();
    }

    // epilogue
#pragma unroll
    for (int mi = 0; mi < 2; mi++) {
#pragma unroll
        for (int ni = 0; ni < 8; ni++) {
            const int rr = m0 + wm + mi * 16 + (lane >> 2);
            const int cc = n0 + wn + ni * 8 + ((lane & 3) << 1);
#pragma unroll
            for (int e = 0; e < 4; e++) {
                const int m = rr + ((e >> 1) << 3);   // +8 for e=2,3
                const int n = cc + (e & 1);
                if (layout == 0) {
                    C[(size_t)m * N + n] = acc[mi][ni][e];
                } else {
                    const int b = m >> 11, s = m & (S_ - 1);
                    const int h = n >> 7,  d = n & (HD_ - 1);
                    C[(((size_t)(b * NH_ + h)) * S_ + s) * HD_ + d] = acc[mi][ni][e];
                }
            }
        }
    }
}

// ---------------------------------------------------------------------------
// RoPE in place on g_q / g_k ([b,h,s,d]). exp2f instead of double pow.
// ---------------------------------------------------------------------------
__global__ void rope_kernel(float* __restrict__ q, float* __restrict__ k,
                            const int* __restrict__ pos_ids)
{
    const int idx = blockIdx.x * blockDim.x + threadIdx.x;
    const int total = B_ * NH_ * S_ * (HD_ / 2);
    if (idx >= total) return;
    const int d = idx & 63;
    int t = idx >> 6;
    const int s = t & (S_ - 1);
    t >>= 11;
    const int h = t & (NH_ - 1);
    const int b = t >> 4;

    const int p = pos_ids[b * S_ + s];
    // inv_f = 10000^(-2d/128) = exp2(-(2d) * log2(10000)/128)
    const float e = (float)(-(2 * d)) * 0.10381025296523008f;
    const float inv_f = exp2f(e);
    const float ang = (float)p * inv_f;
    float sn, cs;
    sincosf(ang, &sn, &cs);

    const size_t base = (((size_t)(b * NH_ + h)) * S_ + s) * HD_ + d;
    const float q1 = q[base], q2 = q[base + 64];
    q[base]      = q1 * cs - q2 * sn;
    q[base + 64] = q2 * cs + q1 * sn;
    const float k1 = k[base], k2 = k[base + 64];
    k[base]      = k1 * cs - k2 * sn;
    k[base + 64] = k2 * cs + k1 * sn;
}

// ---------------------------------------------------------------------------
// Flash attention (fp32, causal) — unchanged from R1.
// ---------------------------------------------------------------------------
#define FTILE 64
#define KTS_STRIDE 68

__global__ __launch_bounds__(256, 1)
void flash_attn(const float* __restrict__ Qg, const float* __restrict__ Kg,
                const float* __restrict__ Vg, float* __restrict__ ctx)
{
    extern __shared__ float sm[];
    float* Qs  = sm;
    float* Kts = Qs + 64 * 128;
    float* Vs  = Kts + 128 * KTS_STRIDE;
    float* Ps  = Vs + 64 * 128;

    const int tid = threadIdx.x;
    const int tx = tid & 15;
    const int ty = tid >> 4;
    const int qt = blockIdx.x;
    const int bh = blockIdx.y;
    const size_t base = (size_t)bh * S_ * HD_;
    const float* Qp = Qg + base + (size_t)qt * FTILE * HD_;

    for (int i = tid; i < FTILE * 32; i += 256) {
        const int r = i >> 5, c4 = (i & 31) << 2;
        *(float4*)&Qs[r * 128 + c4] = *(const float4*)&Qp[(size_t)r * HD_ + c4];
    }

    float m_i[4], l_i[4], acc[4][8];
#pragma unroll
    for (int r = 0; r < 4; r++) {
        m_i[r] = -3.0e30f;
        l_i[r] = 0.0f;
#pragma unroll
        for (int c = 0; c < 8; c++) acc[r][c] = 0.0f;
    }

    const float SCALE = 0.08838834764831845f;

    for (int j = 0; j <= qt; j++) {
        __syncthreads();
        const float* Kp = Kg + base + (size_t)j * FTILE * HD_;
        const float* Vp = Vg + base + (size_t)j * FTILE * HD_;
        for (int i = tid; i < FTILE * 32; i += 256) {
            const int r = i >> 5, c4 = (i & 31) << 2;
            const float4 kv = *(const float4*)&Kp[(size_t)r * HD_ + c4];
            Kts[(c4 + 0) * KTS_STRIDE + r] = kv.x;
            Kts[(c4 + 1) * KTS_STRIDE + r] = kv.y;
            Kts[(c4 + 2) * KTS_STRIDE + r] = kv.z;
            Kts[(c4 + 3) * KTS_STRIDE + r] = kv.w;
            *(float4*)&Vs[r * 128 + c4] = *(const float4*)&Vp[(size_t)r * HD_ + c4];
        }
        __syncthreads();

        float sreg[4][4];
#pragma unroll
        for (int r = 0; r < 4; r++)
#pragma unroll
            for (int c = 0; c < 4; c++) sreg[r][c] = 0.0f;

#pragma unroll 4
        for (int kk = 0; kk < HD_; kk++) {
            const float4 kv = *(const float4*)&Kts[kk * KTS_STRIDE + tx * 4];
            float qv[4];
#pragma unroll
            for (int r = 0; r < 4; r++) qv[r] = Qs[(ty * 4 + r) * 128 + kk];
#pragma unroll
            for (int r = 0; r < 4; r++) {
                sreg[r][0] = fmaf(qv[r], kv.x, sreg[r][0]);
                sreg[r][1] = fmaf(qv[r], kv.y, sreg[r][1]);
                sreg[r][2] = fmaf(qv[r], kv.z, sreg[r][2]);
                sreg[r][3] = fmaf(qv[r], kv.w, sreg[r][3]);
            }
        }

        const bool diag = (j == qt);
#pragma unroll
        for (int r = 0; r < 4; r++) {
            const int qrow = qt * FTILE + ty * 4 + r;
#pragma unroll
            for (int c = 0; c < 4; c++) {
                sreg[r][c] *= SCALE;
                if (diag) {
                    const int kcol = j * FTILE + tx * 4 + c;
                    if (kcol > qrow) sreg[r][c] = -1.0e30f;
                }
            }
        }

#pragma unroll
        for (int r = 0; r < 4; r++) {
            float mloc = fmaxf(fmaxf(sreg[r][0], sreg[r][1]),
                               fmaxf(sreg[r][2], sreg[r][3]));
#pragma unroll
            for (int off = 8; off > 0; off >>= 1)
                mloc = fmaxf(mloc, __shfl_xor_sync(0xffffffffu, mloc, off, 16));
            const float mnew = fmaxf(m_i[r], mloc);
            const float corr = __expf(m_i[r] - mnew);
            float p[4], lloc = 0.0f;
#pragma unroll
            for (int c = 0; c < 4; c++) {
                p[c] = __expf(sreg[r][c] - mnew);
                lloc += p[c];
            }
#pragma unroll
            for (int off = 8; off > 0; off >>= 1)
                lloc += __shfl_xor_sync(0xffffffffu, lloc, off, 16);
            l_i[r] = l_i[r] * corr + lloc;
            m_i[r] = mnew;
#pragma unroll
            for (int c = 0; c < 8; c++) acc[r][c] *= corr;
#pragma unroll
            for (int c = 0; c < 4; c++)
                Ps[(ty * 4 + r) * FTILE + tx * 4 + c] = p[c];
        }
        __syncthreads();

#pragma unroll 4
        for (int c = 0; c < FTILE; c++) {
            const float4 v0 = *(const float4*)&Vs[c * 128 + tx * 8];
            const float4 v1 = *(const float4*)&Vs[c * 128 + tx * 8 + 4];
#pragma unroll
            for (int r = 0; r < 4; r++) {
                const float pv = Ps[(ty * 4 + r) * FTILE + c];
                acc[r][0] = fmaf(pv, v0.x, acc[r][0]);
                acc[r][1] = fmaf(pv, v0.y, acc[r][1]);
                acc[r][2] = fmaf(pv, v0.z, acc[r][2]);
                acc[r][3] = fmaf(pv, v0.w, acc[r][3]);
                acc[r][4] = fmaf(pv, v1.x, acc[r][4]);
                acc[r][5] = fmaf(pv, v1.y, acc[r][5]);
                acc[r][6] = fmaf(pv, v1.z, acc[r][6]);
                acc[r][7] = fmaf(pv, v1.w, acc[r][7]);
            }
        }
    }

    const int b = bh >> 4;
    const int h = bh & (NH_ - 1);
#pragma unroll
    for (int r = 0; r < 4; r++) {
        const float inv = 1.0f / l_i[r];
        const int srow = qt * FTILE + ty * 4 + r;
        float* dst = ctx + (((size_t)(b * S_ + srow)) * NH_ + h) * HD_ + tx * 8;
#pragma unroll
        for (int c = 0; c < 8; c++) dst[c] = acc[r][c] * inv;
    }
}

// ---------------------------------------------------------------------------
extern "C" void kernel_launch(void* const* d_in, const int* in_sizes, int n_in,
                              void* d_out, int out_size)
{
    const float* hs  = (const float*)d_in[0];
    // d_in[1] = attention_mask: deterministically causal, applied analytically
    const int*   pos = (const int*)d_in[2];
    const float* Wq  = (const float*)d_in[3];
    const float* Wk  = (const float*)d_in[4];
    const float* Wv  = (const float*)d_in[5];
    const float* Wo  = (const float*)d_in[6];
    float* out = (float*)d_out;

    float *q, *k, *v, *ctx;
    __nv_bfloat16 *aex, *cex, *wqe, *wke, *wve, *woe;
    cudaGetSymbolAddress((void**)&q,   g_q);
    cudaGetSymbolAddress((void**)&k,   g_k);
    cudaGetSymbolAddress((void**)&v,   g_v);
    cudaGetSymbolAddress((void**)&ctx, g_ctx);
    cudaGetSymbolAddress((void**)&aex, g_aex);
    cudaGetSymbolAddress((void**)&cex, g_cex);
    cudaGetSymbolAddress((void**)&wqe, g_wqe);
    cudaGetSymbolAddress((void**)&wke, g_wke);
    cudaGetSymbolAddress((void**)&wve, g_wve);
    cudaGetSymbolAddress((void**)&woe, g_woe);

    // split/expand inputs + weights to bf16 hi/lo
    const int nA = M_ * K_;
    const int nW = HID_ * K_;
    split_expand<<<(nA + 255) / 256, 256>>>(hs, aex, nA, 0);
    split_expand<<<(nW + 255) / 256, 256>>>(Wq, wqe, nW, 1);
    split_expand<<<(nW + 255) / 256, 256>>>(Wk, wke, nW, 1);
    split_expand<<<(nW + 255) / 256, 256>>>(Wv, wve, nW, 1);
    split_expand<<<(nW + 255) / 256, 256>>>(Wo, woe, nW, 1);

    const dim3 ggrid(HID_ / GBN, M_ / GBM);   // (16, 32)
    gemm_bf16<<<ggrid, 256>>>(aex, wqe, q, HID_, KEX_, 1);
    gemm_bf16<<<ggrid, 256>>>(aex, wke, k, HID_, KEX_, 1);
    gemm_bf16<<<ggrid, 256>>>(aex, wve, v, HID_, KEX_, 1);

    const int rope_total = B_ * NH_ * S_ * (HD_ / 2);
    rope_kernel<<<(rope_total + 255) / 256, 256>>>(q, k, pos);

    const int smem = (64 * 128 + 128 * KTS_STRIDE + 64 * 128 + 64 * 64) * sizeof(float);
    static bool attr_set = false;
    if (!attr_set) {
        cudaFuncSetAttribute(flash_attn, cudaFuncAttributeMaxDynamicSharedMemorySize, smem);
        attr_set = true;
    }
    flash_attn<<<dim3(S_ / FTILE, B_ * NH_), 256, smem>>>(q, k, v, ctx);

    split_expand<<<(nA + 255) / 256, 256>>>(ctx, cex, nA, 0);
    gemm_bf16<<<ggrid, 256>>>(cex, woe, out, HID_, KEX_, 0);
}

// round 5
// speedup vs baseline: 1.9743x; 1.2287x over previous
#include <cuda_runtime.h>
#include <cuda_bf16.h>
#include <cstdint>
#include <cstddef>
#include <math.h>

// Problem constants
#define B_   2
#define S_   2048
#define HID_ 2048
#define NH_  16
#define HD_  128
#define M_   (B_ * S_)     // 4096
#define K_   HID_          // 2048
#define KEX_ (3 * K_)      // 6144 expanded (hi|lo|hi split)

// ---------------------------------------------------------------------------
// Scratch (allocation-free rule: __device__ globals)
// ---------------------------------------------------------------------------
__device__ float g_q[B_ * NH_ * S_ * HD_];     // [b,h,s,d] fp32
__device__ float g_k[B_ * NH_ * S_ * HD_];
__device__ float g_v[B_ * NH_ * S_ * HD_];
__device__ float g_ctx[B_ * S_ * HID_];        // [b,s,h*HD+d] fp32

__device__ __nv_bfloat16 g_aex[(size_t)M_ * KEX_];     // hs  expanded
__device__ __nv_bfloat16 g_cex[(size_t)M_ * KEX_];     // ctx expanded
__device__ __nv_bfloat16 g_wqe[(size_t)HID_ * KEX_];   // weights expanded
__device__ __nv_bfloat16 g_wke[(size_t)HID_ * KEX_];
__device__ __nv_bfloat16 g_wve[(size_t)HID_ * KEX_];
__device__ __nv_bfloat16 g_woe[(size_t)HID_ * KEX_];

// ---------------------------------------------------------------------------
// fp32 -> bf16 hi/lo split, expanded-K layout (vectorized: 4 elems/thread).
// mode 0 ("A" side):  [hi | lo | hi]
// mode 1 ("W" side):  [hi | hi | lo]
// A'·W'^T over Kex = Ah·Wh + Al·Wh + Ah·Wl  (exact to ~2^-18).
// ---------------------------------------------------------------------------
__global__ void split_expand(const float* __restrict__ X,
                             __nv_bfloat16* __restrict__ Y,
                             int total4, int mode)
{
    const int t = blockIdx.x * blockDim.x + threadIdx.x;
    if (t >= total4) return;
    const int idx = t * 4;
    const int r = idx >> 11;           // / 2048
    const int k = idx & (K_ - 1);
    const float4 x = *(const float4*)(X + idx);

    __nv_bfloat16 hi[4], lo[4];
    const float xs[4] = {x.x, x.y, x.z, x.w};
#pragma unroll
    for (int i = 0; i < 4; i++) {
        hi[i] = __float2bfloat16_rn(xs[i]);
        lo[i] = __float2bfloat16_rn(xs[i] - __bfloat162float(hi[i]));
    }
    __nv_bfloat16* dst = Y + (size_t)r * KEX_ + k;
    // 8-byte stores
    *(uint2*)(dst)            = *(const uint2*)hi;
    if (mode == 0) {
        *(uint2*)(dst + K_)       = *(const uint2*)lo;
        *(uint2*)(dst + 2 * K_)   = *(const uint2*)hi;
    } else {
        *(uint2*)(dst + K_)       = *(const uint2*)hi;
        *(uint2*)(dst + 2 * K_)   = *(const uint2*)lo;
    }
}

// ---------------------------------------------------------------------------
// bf16 mma.sync GEMM:  C[M,N] = A'[M,Kex] · W'[N,Kex]^T   (fp32 accumulate)
// Tiles 128x128x64, 8 warps (4m x 2n), warp tile 32x64, m16n8k16 mma.
// 3-stage cp.async pipeline; dynamic smem 108KB; 2 CTAs/SM.
// smem rows padded to 72 bf16 (144B) -> conflict-free ldmatrix.
// layout 0: C[m*N+n]; layout 1: scatter to [b,h,s,d].
// ---------------------------------------------------------------------------
#define GBM 128
#define GBN 128
#define GBK 64
#define LDP 72                      // padded smem row length (bf16)
#define GSTG 3                      // pipeline stages
#define STG_B (GBM * LDP * 2)       // 18432 bytes per matrix per stage
#define GEMM_SMEM (2 * GSTG * STG_B) // 110592

__device__ __forceinline__ void cpasync16(unsigned int smem_dst, const void* gsrc) {
    asm volatile("cp.async.cg.shared.global [%0], [%1], 16;\n" :: "r"(smem_dst), "l"(gsrc));
}
__device__ __forceinline__ void cp_commit() {
    asm volatile("cp.async.commit_group;\n");
}

__device__ __forceinline__ void ldm_x4(unsigned int& r0, unsigned int& r1,
                                       unsigned int& r2, unsigned int& r3,
                                       unsigned int addr) {
    asm volatile("ldmatrix.sync.aligned.m8n8.x4.shared.b16 {%0,%1,%2,%3}, [%4];\n"
                 : "=r"(r0), "=r"(r1), "=r"(r2), "=r"(r3) : "r"(addr));
}

__device__ __forceinline__ void mma_bf16(float* c, const unsigned int* a,
                                         const unsigned int* b) {
    asm volatile(
        "mma.sync.aligned.m16n8k16.row.col.f32.bf16.bf16.f32 "
        "{%0,%1,%2,%3}, {%4,%5,%6,%7}, {%8,%9}, {%0,%1,%2,%3};\n"
        : "+f"(c[0]), "+f"(c[1]), "+f"(c[2]), "+f"(c[3])
        : "r"(a[0]), "r"(a[1]), "r"(a[2]), "r"(a[3]), "r"(b[0]), "r"(b[1]));
}

__global__ __launch_bounds__(256, 2)
void gemm_bf16(const __nv_bfloat16* __restrict__ A,
               const __nv_bfloat16* __restrict__ W,
               float* __restrict__ C, int N, int Kex, int layout)
{
    extern __shared__ char gsm[];
    const unsigned int sbase = (unsigned int)__cvta_generic_to_shared(gsm);
    // layout: [As0|As1|As2|Bs0|Bs1|Bs2], each STG_B bytes
    const unsigned int sBoff = GSTG * STG_B;

    const int tid  = threadIdx.x;
    const int lane = tid & 31;
    const int w    = tid >> 5;
    const int wm   = (w >> 1) << 5;   // 0,32,64,96
    const int wn   = (w & 1) << 6;    // 0,64
    const int m0   = blockIdx.y * GBM;
    const int n0   = blockIdx.x * GBN;

    float acc[2][8][4];
#pragma unroll
    for (int mi = 0; mi < 2; mi++)
#pragma unroll
        for (int ni = 0; ni < 8; ni++)
#pragma unroll
            for (int e = 0; e < 4; e++) acc[mi][ni][e] = 0.0f;

    // load mapping: 128 rows x 8 chunks(16B) = 1024 chunks per matrix;
    // 256 threads x 4 iters. r = tid>>3 (+32*i), c = tid&7.
    const int lr = tid >> 3;
    const int lc = tid & 7;

    const int NT = Kex / GBK;   // 96

    auto load_stage = [&](int kt, int s) {
        const unsigned int aD = sbase + s * STG_B;
        const unsigned int bD = sbase + sBoff + s * STG_B;
        const __nv_bfloat16* Ap = A + (size_t)m0 * Kex + kt * GBK + lc * 8;
        const __nv_bfloat16* Wp = W + (size_t)n0 * Kex + kt * GBK + lc * 8;
#pragma unroll
        for (int i = 0; i < 4; i++) {
            const int row = lr + i * 32;
            const unsigned int off = (unsigned int)(row * LDP + lc * 8) * 2;
            cpasync16(aD + off, Ap + (size_t)row * Kex);
            cpasync16(bD + off, Wp + (size_t)row * Kex);
        }
        cp_commit();
    };

    load_stage(0, 0);
    load_stage(1, 1);

    for (int kt = 0; kt < NT; kt++) {
        if (kt + 1 < NT) {
            asm volatile("cp.async.wait_group 1;\n");
        } else {
            asm volatile("cp.async.wait_group 0;\n");
        }
        __syncthreads();   // stage kt%3 data visible; all done with stage (kt-1)%3

        if (kt + 2 < NT) load_stage(kt + 2, (kt + 2) % GSTG);

        const int s = kt % GSTG;
        const unsigned int aBase = sbase + s * STG_B;
        const unsigned int bBase = sbase + sBoff + s * STG_B;

#pragma unroll
        for (int ks = 0; ks < 4; ks++) {
            unsigned int afr[2][4], bfr[8][2];
#pragma unroll
            for (int mi = 0; mi < 2; mi++) {
                const int row = wm + mi * 16 + (lane & 15);
                const unsigned int addr =
                    aBase + (unsigned int)(row * LDP + ks * 16 + (lane >> 4) * 8) * 2;
                ldm_x4(afr[mi][0], afr[mi][1], afr[mi][2], afr[mi][3], addr);
            }
#pragma unroll
            for (int p = 0; p < 4; p++) {
                const int nrow = wn + p * 16 + (lane & 7) + ((lane >> 4) << 3);
                const int chunk = (lane >> 3) & 1;
                const unsigned int addr =
                    bBase + (unsigned int)(nrow * LDP + ks * 16 + chunk * 8) * 2;
                ldm_x4(bfr[2 * p][0], bfr[2 * p][1], bfr[2 * p + 1][0], bfr[2 * p + 1][1], addr);
            }
#pragma unroll
            for (int mi = 0; mi < 2; mi++)
#pragma unroll
                for (int ni = 0; ni < 8; ni++)
                    mma_bf16(acc[mi][ni], afr[mi], bfr[ni]);
        }
    }

    // epilogue
#pragma unroll
    for (int mi = 0; mi < 2; mi++) {
#pragma unroll
        for (int ni = 0; ni < 8; ni++) {
            const int rr = m0 + wm + mi * 16 + (lane >> 2);
            const int cc = n0 + wn + ni * 8 + ((lane & 3) << 1);
#pragma unroll
            for (int e = 0; e < 4; e++) {
                const int m = rr + ((e >> 1) << 3);   // +8 for e=2,3
                const int n = cc + (e & 1);
                if (layout == 0) {
                    C[(size_t)m * N + n] = acc[mi][ni][e];
                } else {
                    const int b = m >> 11, s = m & (S_ - 1);
                    const int h = n >> 7,  d = n & (HD_ - 1);
                    C[(((size_t)(b * NH_ + h)) * S_ + s) * HD_ + d] = acc[mi][ni][e];
                }
            }
        }
    }
}

// ---------------------------------------------------------------------------
// RoPE in place on g_q / g_k ([b,h,s,d]).
// ---------------------------------------------------------------------------
__global__ void rope_kernel(float* __restrict__ q, float* __restrict__ k,
                            const int* __restrict__ pos_ids)
{
    const int idx = blockIdx.x * blockDim.x + threadIdx.x;
    const int total = B_ * NH_ * S_ * (HD_ / 2);
    if (idx >= total) return;
    const int d = idx & 63;
    int t = idx >> 6;
    const int s = t & (S_ - 1);
    t >>= 11;
    const int h = t & (NH_ - 1);
    const int b = t >> 4;

    const int p = pos_ids[b * S_ + s];
    const float e = (float)(-(2 * d)) * 0.10381025296523008f;
    const float inv_f = exp2f(e);
    const float ang = (float)p * inv_f;
    float sn, cs;
    sincosf(ang, &sn, &cs);

    const size_t base = (((size_t)(b * NH_ + h)) * S_ + s) * HD_ + d;
    const float q1 = q[base], q2 = q[base + 64];
    q[base]      = q1 * cs - q2 * sn;
    q[base + 64] = q2 * cs + q1 * sn;
    const float k1 = k[base], k2 = k[base + 64];
    k[base]      = k1 * cs - k2 * sn;
    k[base + 64] = k2 * cs + k1 * sn;
}

// ---------------------------------------------------------------------------
// Flash attention (fp32, causal) — unchanged (known good).
// ---------------------------------------------------------------------------
#define FTILE 64
#define KTS_STRIDE 68

__global__ __launch_bounds__(256, 1)
void flash_attn(const float* __restrict__ Qg, const float* __restrict__ Kg,
                const float* __restrict__ Vg, float* __restrict__ ctx)
{
    extern __shared__ float sm[];
    float* Qs  = sm;
    float* Kts = Qs + 64 * 128;
    float* Vs  = Kts + 128 * KTS_STRIDE;
    float* Ps  = Vs + 64 * 128;

    const int tid = threadIdx.x;
    const int tx = tid & 15;
    const int ty = tid >> 4;
    const int qt = blockIdx.x;
    const int bh = blockIdx.y;
    const size_t base = (size_t)bh * S_ * HD_;
    const float* Qp = Qg + base + (size_t)qt * FTILE * HD_;

    for (int i = tid; i < FTILE * 32; i += 256) {
        const int r = i >> 5, c4 = (i & 31) << 2;
        *(float4*)&Qs[r * 128 + c4] = *(const float4*)&Qp[(size_t)r * HD_ + c4];
    }

    float m_i[4], l_i[4], acc[4][8];
#pragma unroll
    for (int r = 0; r < 4; r++) {
        m_i[r] = -3.0e30f;
        l_i[r] = 0.0f;
#pragma unroll
        for (int c = 0; c < 8; c++) acc[r][c] = 0.0f;
    }

    const float SCALE = 0.08838834764831845f;

    for (int j = 0; j <= qt; j++) {
        __syncthreads();
        const float* Kp = Kg + base + (size_t)j * FTILE * HD_;
        const float* Vp = Vg + base + (size_t)j * FTILE * HD_;
        for (int i = tid; i < FTILE * 32; i += 256) {
            const int r = i >> 5, c4 = (i & 31) << 2;
            const float4 kv = *(const float4*)&Kp[(size_t)r * HD_ + c4];
            Kts[(c4 + 0) * KTS_STRIDE + r] = kv.x;
            Kts[(c4 + 1) * KTS_STRIDE + r] = kv.y;
            Kts[(c4 + 2) * KTS_STRIDE + r] = kv.z;
            Kts[(c4 + 3) * KTS_STRIDE + r] = kv.w;
            *(float4*)&Vs[r * 128 + c4] = *(const float4*)&Vp[(size_t)r * HD_ + c4];
        }
        __syncthreads();

        float sreg[4][4];
#pragma unroll
        for (int r = 0; r < 4; r++)
#pragma unroll
            for (int c = 0; c < 4; c++) sreg[r][c] = 0.0f;

#pragma unroll 4
        for (int kk = 0; kk < HD_; kk++) {
            const float4 kv = *(const float4*)&Kts[kk * KTS_STRIDE + tx * 4];
            float qv[4];
#pragma unroll
            for (int r = 0; r < 4; r++) qv[r] = Qs[(ty * 4 + r) * 128 + kk];
#pragma unroll
            for (int r = 0; r < 4; r++) {
                sreg[r][0] = fmaf(qv[r], kv.x, sreg[r][0]);
                sreg[r][1] = fmaf(qv[r], kv.y, sreg[r][1]);
                sreg[r][2] = fmaf(qv[r], kv.z, sreg[r][2]);
                sreg[r][3] = fmaf(qv[r], kv.w, sreg[r][3]);
            }
        }

        const bool diag = (j == qt);
#pragma unroll
        for (int r = 0; r < 4; r++) {
            const int qrow = qt * FTILE + ty * 4 + r;
#pragma unroll
            for (int c = 0; c < 4; c++) {
                sreg[r][c] *= SCALE;
                if (diag) {
                    const int kcol = j * FTILE + tx * 4 + c;
                    if (kcol > qrow) sreg[r][c] = -1.0e30f;
                }
            }
        }

#pragma unroll
        for (int r = 0; r < 4; r++) {
            float mloc = fmaxf(fmaxf(sreg[r][0], sreg[r][1]),
                               fmaxf(sreg[r][2], sreg[r][3]));
#pragma unroll
            for (int off = 8; off > 0; off >>= 1)
                mloc = fmaxf(mloc, __shfl_xor_sync(0xffffffffu, mloc, off, 16));
            const float mnew = fmaxf(m_i[r], mloc);
            const float corr = __expf(m_i[r] - mnew);
            float p[4], lloc = 0.0f;
#pragma unroll
            for (int c = 0; c < 4; c++) {
                p[c] = __expf(sreg[r][c] - mnew);
                lloc += p[c];
            }
#pragma unroll
            for (int off = 8; off > 0; off >>= 1)
                lloc += __shfl_xor_sync(0xffffffffu, lloc, off, 16);
            l_i[r] = l_i[r] * corr + lloc;
            m_i[r] = mnew;
#pragma unroll
            for (int c = 0; c < 8; c++) acc[r][c] *= corr;
#pragma unroll
            for (int c = 0; c < 4; c++)
                Ps[(ty * 4 + r) * FTILE + tx * 4 + c] = p[c];
        }
        __syncthreads();

#pragma unroll 4
        for (int c = 0; c < FTILE; c++) {
            const float4 v0 = *(const float4*)&Vs[c * 128 + tx * 8];
            const float4 v1 = *(const float4*)&Vs[c * 128 + tx * 8 + 4];
#pragma unroll
            for (int r = 0; r < 4; r++) {
                const float pv = Ps[(ty * 4 + r) * FTILE + c];
                acc[r][0] = fmaf(pv, v0.x, acc[r][0]);
                acc[r][1] = fmaf(pv, v0.y, acc[r][1]);
                acc[r][2] = fmaf(pv, v0.z, acc[r][2]);
                acc[r][3] = fmaf(pv, v0.w, acc[r][3]);
                acc[r][4] = fmaf(pv, v1.x, acc[r][4]);
                acc[r][5] = fmaf(pv, v1.y, acc[r][5]);
                acc[r][6] = fmaf(pv, v1.z, acc[r][6]);
                acc[r][7] = fmaf(pv, v1.w, acc[r][7]);
            }
        }
    }

    const int b = bh >> 4;
    const int h = bh & (NH_ - 1);
#pragma unroll
    for (int r = 0; r < 4; r++) {
        const float inv = 1.0f / l_i[r];
        const int srow = qt * FTILE + ty * 4 + r;
        float* dst = ctx + (((size_t)(b * S_ + srow)) * NH_ + h) * HD_ + tx * 8;
#pragma unroll
        for (int c = 0; c < 8; c++) dst[c] = acc[r][c] * inv;
    }
}

// ---------------------------------------------------------------------------
extern "C" void kernel_launch(void* const* d_in, const int* in_sizes, int n_in,
                              void* d_out, int out_size)
{
    const float* hs  = (const float*)d_in[0];
    // d_in[1] = attention_mask: deterministically causal, applied analytically
    const int*   pos = (const int*)d_in[2];
    const float* Wq  = (const float*)d_in[3];
    const float* Wk  = (const float*)d_in[4];
    const float* Wv  = (const float*)d_in[5];
    const float* Wo  = (const float*)d_in[6];
    float* out = (float*)d_out;

    float *q, *k, *v, *ctx;
    __nv_bfloat16 *aex, *cex, *wqe, *wke, *wve, *woe;
    cudaGetSymbolAddress((void**)&q,   g_q);
    cudaGetSymbolAddress((void**)&k,   g_k);
    cudaGetSymbolAddress((void**)&v,   g_v);
    cudaGetSymbolAddress((void**)&ctx, g_ctx);
    cudaGetSymbolAddress((void**)&aex, g_aex);
    cudaGetSymbolAddress((void**)&cex, g_cex);
    cudaGetSymbolAddress((void**)&wqe, g_wqe);
    cudaGetSymbolAddress((void**)&wke, g_wke);
    cudaGetSymbolAddress((void**)&wve, g_wve);
    cudaGetSymbolAddress((void**)&woe, g_woe);

    const int nA4 = (M_ * K_) / 4;
    const int nW4 = (HID_ * K_) / 4;
    split_expand<<<(nA4 + 255) / 256, 256>>>(hs, aex, nA4, 0);
    split_expand<<<(nW4 + 255) / 256, 256>>>(Wq, wqe, nW4, 1);
    split_expand<<<(nW4 + 255) / 256, 256>>>(Wk, wke, nW4, 1);
    split_expand<<<(nW4 + 255) / 256, 256>>>(Wv, wve, nW4, 1);
    split_expand<<<(nW4 + 255) / 256, 256>>>(Wo, woe, nW4, 1);

    static bool attr_set = false;
    const int fsmem = (64 * 128 + 128 * KTS_STRIDE + 64 * 128 + 64 * 64) * sizeof(float);
    if (!attr_set) {
        cudaFuncSetAttribute(gemm_bf16, cudaFuncAttributeMaxDynamicSharedMemorySize, GEMM_SMEM);
        cudaFuncSetAttribute(flash_attn, cudaFuncAttributeMaxDynamicSharedMemorySize, fsmem);
        attr_set = true;
    }

    const dim3 ggrid(HID_ / GBN, M_ / GBM);   // (16, 32)
    gemm_bf16<<<ggrid, 256, GEMM_SMEM>>>(aex, wqe, q, HID_, KEX_, 1);
    gemm_bf16<<<ggrid, 256, GEMM_SMEM>>>(aex, wke, k, HID_, KEX_, 1);
    gemm_bf16<<<ggrid, 256, GEMM_SMEM>>>(aex, wve, v, HID_, KEX_, 1);

    const int rope_total = B_ * NH_ * S_ * (HD_ / 2);
    rope_kernel<<<(rope_total + 255) / 256, 256>>>(q, k, pos);

    flash_attn<<<dim3(S_ / FTILE, B_ * NH_), 256, fsmem>>>(q, k, v, ctx);

    split_expand<<<(nA4 + 255) / 256, 256>>>(ctx, cex, nA4, 0);
    gemm_bf16<<<ggrid, 256, GEMM_SMEM>>>(cex, woe, out, HID_, KEX_, 0);
}